// round 1
// baseline (speedup 1.0000x reference)
#include <cuda_runtime.h>
#include <cuda_bf16.h>

// GraphSAGE 2-layer encoder.
// Layer l: mean = scatter_mean(x[src] -> dst); y = mean @ Wl^T + bl + x @ Wr^T
// h = relu(layer1(emb)); out = layer2(h)

#define F1 64
#define F2 128
#define NMAX 50016          // 50000 rounded up to block granularity
#define EMAX 640000

// scratch (no allocations allowed -> device globals)
__device__ float g_deg[NMAX];
__device__ float g_agg1[(size_t)NMAX * F1];
__device__ float g_h[(size_t)NMAX * F2];
__device__ float g_agg2[(size_t)NMAX * F2];

// ---------------------------------------------------------------------------
// zero scratch (float4 stores)
// ---------------------------------------------------------------------------
__global__ void zero_kernel(int n1, int n2, int nd) {
    int i = blockIdx.x * blockDim.x + threadIdx.x;
    float4 z = make_float4(0.f, 0.f, 0.f, 0.f);
    if (i < n1) ((float4*)g_agg1)[i] = z;
    if (i < n2) ((float4*)g_agg2)[i] = z;
    if (i < nd) ((float4*)g_deg)[i] = z;
}

// ---------------------------------------------------------------------------
// scatter layer 1: agg1[dst] += emb[src]  (64 floats = 16 float4 per edge)
// also computes degree (once, reused by both layers)
// ---------------------------------------------------------------------------
__global__ void scatter1_kernel(const int* __restrict__ src,
                                const int* __restrict__ dst,
                                const float* __restrict__ emb, int E) {
    int idx = blockIdx.x * blockDim.x + threadIdx.x;
    if (idx >= E * 16) return;
    int e = idx >> 4, c = idx & 15;
    int s = src[e], d = dst[e];
    float4 v = ((const float4*)emb)[(size_t)s * 16 + c];
    atomicAdd(((float4*)g_agg1) + (size_t)d * 16 + c, v);
    if (c == 0) atomicAdd(g_deg + d, 1.0f);
}

// ---------------------------------------------------------------------------
// scatter layer 2: agg2[dst] += h[src]  (128 floats = 32 float4 per edge)
// ---------------------------------------------------------------------------
__global__ void scatter2_kernel(const int* __restrict__ src,
                                const int* __restrict__ dst, int E) {
    int idx = blockIdx.x * blockDim.x + threadIdx.x;
    if (idx >= E * 32) return;
    int e = idx >> 5, c = idx & 31;
    int s = src[e], d = dst[e];
    float4 v = ((const float4*)g_h)[(size_t)s * 32 + c];
    atomicAdd(((float4*)g_agg2) + (size_t)d * 32 + c, v);
}

// ---------------------------------------------------------------------------
// layer 1 transform: h[n][o] = relu( mean1[n] . W1l[o] + b1l[o] + emb[n] . W1r[o] )
// blockDim = 256: o = tid & 127, jgrp = tid >> 7 (each half-block does 4 of 8 nodes)
// 32 nodes per block, 4 iterations of 8 staged nodes.
// Weights in smem transposed [k][o] with rotation swizzle (o+k)&127:
//   - global read W[o*64+k] coalesced
//   - smem write banks = (o + 129k) % 32 -> conflict-free over k
//   - smem read (fixed k, consecutive o) -> rotation keeps it conflict-free
// ---------------------------------------------------------------------------
__global__ void layer1_kernel(const float* __restrict__ emb,
                              const float* __restrict__ W1l,
                              const float* __restrict__ b1l,
                              const float* __restrict__ W1r, int N) {
    extern __shared__ float sh[];
    float* sWl = sh;                   // 64*128
    float* sWr = sWl + F1 * F2;        // 64*128
    float* sX  = sWr + F1 * F2;        // 8*64
    float* sM  = sX + 8 * F1;          // 8*64
    int tid = threadIdx.x;

    for (int i = tid; i < F2 * F1; i += 256) {
        int o = i >> 6, k = i & 63;
        int sidx = k * F2 + ((o + k) & 127);
        sWl[sidx] = W1l[i];
        sWr[sidx] = W1r[i];
    }
    __syncthreads();

    int o = tid & 127;
    int jgrp = tid >> 7;
    float bias = b1l[o];
    int nbase = blockIdx.x * 32;

    for (int it = 0; it < 4; it++) {
        int n0 = nbase + it * 8;
        __syncthreads();
        for (int i = tid; i < 8 * F1; i += 256) {
            int j = i >> 6, k = i & 63;
            int n = n0 + j;
            if (n < N) {
                float rd = 1.0f / fmaxf(g_deg[n], 1.0f);
                sX[i] = emb[(size_t)n * F1 + k];
                sM[i] = g_agg1[(size_t)n * F1 + k] * rd;
            }
        }
        __syncthreads();

        float a0 = bias, a1 = bias, a2 = bias, a3 = bias;
        const float* xj = sX + jgrp * 4 * F1;
        const float* mj = sM + jgrp * 4 * F1;
#pragma unroll 16
        for (int k = 0; k < F1; k++) {
            int sidx = k * F2 + ((o + k) & 127);
            float wl = sWl[sidx];
            float wr = sWr[sidx];
            a0 += mj[k] * wl;        a0 += xj[k] * wr;
            a1 += mj[64 + k] * wl;   a1 += xj[64 + k] * wr;
            a2 += mj[128 + k] * wl;  a2 += xj[128 + k] * wr;
            a3 += mj[192 + k] * wl;  a3 += xj[192 + k] * wr;
        }
        int n = n0 + jgrp * 4;
        if (n     < N) g_h[(size_t)(n)     * F2 + o] = fmaxf(a0, 0.f);
        if (n + 1 < N) g_h[(size_t)(n + 1) * F2 + o] = fmaxf(a1, 0.f);
        if (n + 2 < N) g_h[(size_t)(n + 2) * F2 + o] = fmaxf(a2, 0.f);
        if (n + 3 < N) g_h[(size_t)(n + 3) * F2 + o] = fmaxf(a3, 0.f);
    }
}

// ---------------------------------------------------------------------------
// layer 2 transform: out[n][o] = mean2[n] . W2l[o] + b2l[o] + h[n] . W2r[o]
// same scheme, K = 128
// ---------------------------------------------------------------------------
__global__ void layer2_kernel(const float* __restrict__ W2l,
                              const float* __restrict__ b2l,
                              const float* __restrict__ W2r,
                              float* __restrict__ out, int N) {
    extern __shared__ float sh[];
    float* sWl = sh;                   // 128*128
    float* sWr = sWl + F2 * F2;        // 128*128
    float* sX  = sWr + F2 * F2;        // 8*128
    float* sM  = sX + 8 * F2;          // 8*128
    int tid = threadIdx.x;

    for (int i = tid; i < F2 * F2; i += 256) {
        int o = i >> 7, k = i & 127;
        int sidx = k * F2 + ((o + k) & 127);
        sWl[sidx] = W2l[i];
        sWr[sidx] = W2r[i];
    }
    __syncthreads();

    int o = tid & 127;
    int jgrp = tid >> 7;
    float bias = b2l[o];
    int nbase = blockIdx.x * 32;

    for (int it = 0; it < 4; it++) {
        int n0 = nbase + it * 8;
        __syncthreads();
        for (int i = tid; i < 8 * F2; i += 256) {
            int j = i >> 7, k = i & 127;
            int n = n0 + j;
            if (n < N) {
                float rd = 1.0f / fmaxf(g_deg[n], 1.0f);
                sX[i] = g_h[(size_t)n * F2 + k];
                sM[i] = g_agg2[(size_t)n * F2 + k] * rd;
            }
        }
        __syncthreads();

        float a0 = bias, a1 = bias, a2 = bias, a3 = bias;
        const float* xj = sX + jgrp * 4 * F2;
        const float* mj = sM + jgrp * 4 * F2;
#pragma unroll 16
        for (int k = 0; k < F2; k++) {
            int sidx = k * F2 + ((o + k) & 127);
            float wl = sWl[sidx];
            float wr = sWr[sidx];
            a0 += mj[k] * wl;         a0 += xj[k] * wr;
            a1 += mj[128 + k] * wl;   a1 += xj[128 + k] * wr;
            a2 += mj[256 + k] * wl;   a2 += xj[256 + k] * wr;
            a3 += mj[384 + k] * wl;   a3 += xj[384 + k] * wr;
        }
        int n = n0 + jgrp * 4;
        if (n     < N) out[(size_t)(n)     * F2 + o] = a0;
        if (n + 1 < N) out[(size_t)(n + 1) * F2 + o] = a1;
        if (n + 2 < N) out[(size_t)(n + 2) * F2 + o] = a2;
        if (n + 3 < N) out[(size_t)(n + 3) * F2 + o] = a3;
    }
}

// ---------------------------------------------------------------------------
extern "C" void kernel_launch(void* const* d_in, const int* in_sizes, int n_in,
                              void* d_out, int out_size) {
    const int*   edge = (const int*)d_in[0];
    const float* emb  = (const float*)d_in[1];
    const float* W1l  = (const float*)d_in[2];
    const float* b1l  = (const float*)d_in[3];
    const float* W1r  = (const float*)d_in[4];
    const float* W2l  = (const float*)d_in[5];
    const float* b2l  = (const float*)d_in[6];
    const float* W2r  = (const float*)d_in[7];
    float* out = (float*)d_out;

    int E = in_sizes[0] / 2;
    int N = in_sizes[1] / F1;
    const int* src = edge;
    const int* dst = edge + E;

    int smem1 = (F1 * F2 * 2 + 8 * F1 * 2) * (int)sizeof(float);   // ~68 KB
    int smem2 = (F2 * F2 * 2 + 8 * F2 * 2) * (int)sizeof(float);   // ~136 KB
    cudaFuncSetAttribute(layer1_kernel, cudaFuncAttributeMaxDynamicSharedMemorySize, smem1);
    cudaFuncSetAttribute(layer2_kernel, cudaFuncAttributeMaxDynamicSharedMemorySize, smem2);

    // zero scratch
    {
        int n1 = N * (F1 / 4);      // agg1 in float4
        int n2 = N * (F2 / 4);      // agg2 in float4
        int nd = (N + 3) / 4;       // deg  in float4
        int mx = n2;
        zero_kernel<<<(mx + 255) / 256, 256>>>(n1, n2, nd);
    }

    // layer 1 aggregation (+ degree)
    {
        long long total = (long long)E * 16;
        scatter1_kernel<<<(int)((total + 255) / 256), 256>>>(src, dst, emb, E);
    }

    // layer 1 transform
    {
        int blocks = (N + 31) / 32;
        layer1_kernel<<<blocks, 256, smem1>>>(emb, W1l, b1l, W1r, N);
    }

    // layer 2 aggregation
    {
        long long total = (long long)E * 32;
        scatter2_kernel<<<(int)((total + 255) / 256), 256>>>(src, dst, E);
    }

    // layer 2 transform
    {
        int blocks = (N + 31) / 32;
        layer2_kernel<<<blocks, 256, smem2>>>(W2l, b2l, W2r, out, N);
    }
}

// round 3
// speedup vs baseline: 1.8080x; 1.8080x over previous
#include <cuda_runtime.h>
#include <cuda_bf16.h>

// GraphSAGE 2-layer encoder.
// Layer l: mean = scatter_mean(x[src] -> dst); y = [mean|x] @ [Wl^T; Wr^T] + bl
// h = relu(layer1(emb)); out = layer2(h)

#define F1 64
#define F2 128
#define NMAX 50048          // 50000 rounded up to 128
#define KC 16

// scratch (no allocations allowed -> device globals; referenced ONLY in device code)
__device__ float g_deg[NMAX];
__device__ float g_agg1[(size_t)NMAX * F1];
__device__ float g_h[(size_t)NMAX * F2];
__device__ float g_agg2[(size_t)NMAX * F2];
__device__ float g_B1[128 * 128];   // [k][o], k<64: W1l^T, k>=64: W1r^T
__device__ float g_B2[256 * 128];   // [k][o], k<128: W2l^T, k>=128: W2r^T

// ---------------------------------------------------------------------------
// zero scratch (float4 stores)
// ---------------------------------------------------------------------------
__global__ void zero_kernel(int n1, int n2, int nd) {
    int i = blockIdx.x * blockDim.x + threadIdx.x;
    float4 z = make_float4(0.f, 0.f, 0.f, 0.f);
    if (i < n1) ((float4*)g_agg1)[i] = z;
    if (i < n2) ((float4*)g_agg2)[i] = z;
    if (i < nd) ((float4*)g_deg)[i] = z;
}

// ---------------------------------------------------------------------------
// pack weights transposed+concatenated: B[k][o]
// ---------------------------------------------------------------------------
__global__ void pack_kernel(const float* __restrict__ W1l, const float* __restrict__ W1r,
                            const float* __restrict__ W2l, const float* __restrict__ W2r) {
    int i = blockIdx.x * blockDim.x + threadIdx.x;
    if (i < 128 * 128) {
        int k = i >> 7, o = i & 127;
        g_B1[i] = (k < 64) ? W1l[o * 64 + k] : W1r[o * 64 + (k - 64)];
    }
    if (i < 256 * 128) {
        int k = i >> 7, o = i & 127;
        g_B2[i] = (k < 128) ? W2l[o * 128 + k] : W2r[o * 128 + (k - 128)];
    }
}

// ---------------------------------------------------------------------------
// scatter layer 1: agg1[dst] += emb[src]  (64 floats = 16 float4 per edge)
// also computes degree
// ---------------------------------------------------------------------------
__global__ void scatter1_kernel(const int* __restrict__ src,
                                const int* __restrict__ dst,
                                const float* __restrict__ emb, int E) {
    int idx = blockIdx.x * blockDim.x + threadIdx.x;
    if (idx >= E * 16) return;
    int e = idx >> 4, c = idx & 15;
    int s = src[e], d = dst[e];
    float4 v = ((const float4*)emb)[(size_t)s * 16 + c];
    atomicAdd(((float4*)g_agg1) + (size_t)d * 16 + c, v);
    if (c == 0) atomicAdd(g_deg + d, 1.0f);
}

// ---------------------------------------------------------------------------
// scatter layer 2: agg2[dst] += h[src]  (128 floats = 32 float4 per edge)
// ---------------------------------------------------------------------------
__global__ void scatter2_kernel(const int* __restrict__ src,
                                const int* __restrict__ dst, int E) {
    int idx = blockIdx.x * blockDim.x + threadIdx.x;
    if (idx >= E * 32) return;
    int e = idx >> 5, c = idx & 31;
    int s = src[e], d = dst[e];
    float4 v = ((const float4*)g_h)[(size_t)s * 32 + c];
    atomicAdd(((float4*)g_agg2) + (size_t)d * 32 + c, v);
}

// ---------------------------------------------------------------------------
// Register-tiled GEMM: C[N,128] = [Agg*rd | X] @ Bw + bias, optional relu.
// Block: 128 rows x 128 cols, 256 threads, 8x8 micro-tile per thread.
// Scratch buffers selected INSIDE device code via template flag L1
// (device globals must not be passed as host-side kernel args).
// ---------------------------------------------------------------------------
template<int K, bool RELU, bool L1>
__global__ __launch_bounds__(256, 2)
void gemm_kernel(const float* __restrict__ Xin,
                 const float* __restrict__ bias,
                 float* __restrict__ Cout, int N) {
    constexpr int F = K / 2;
    const float* Agg = L1 ? g_agg1 : g_agg2;
    const float* Bw  = L1 ? g_B1   : g_B2;
    const float* X   = L1 ? Xin    : g_h;
    float*       C   = L1 ? g_h    : Cout;

    __shared__ float sA[KC * 132];
    __shared__ float sB[KC * 128];
    __shared__ float sRD[128];

    int tid = threadIdx.x;
    int nbase = blockIdx.x * 128;

    if (tid < 128) {
        int n = nbase + tid;
        sRD[tid] = (n < N) ? 1.0f / fmaxf(g_deg[n], 1.0f) : 0.f;
    }
    __syncthreads();

    int tx = tid & 15, ty = tid >> 4;
    int m0 = ty * 8, o0 = tx * 8;

    // accumulators init with bias
    float4 bb0 = ((const float4*)(bias + o0))[0];
    float4 bb1 = ((const float4*)(bias + o0))[1];
    float acc[8][8];
#pragma unroll
    for (int i = 0; i < 8; i++) {
        acc[i][0] = bb0.x; acc[i][1] = bb0.y; acc[i][2] = bb0.z; acc[i][3] = bb0.w;
        acc[i][4] = bb1.x; acc[i][5] = bb1.y; acc[i][6] = bb1.z; acc[i][7] = bb1.w;
    }

    float4 pa[2], pb[2];

    auto loadAB = [&](int k0) {
#pragma unroll
        for (int r = 0; r < 2; r++) {
            int v = tid + 256 * r;
            int m = v >> 2, kq = v & 3;
            int n = nbase + m;
            float4 val = make_float4(0.f, 0.f, 0.f, 0.f);
            if (n < N) {
                if (k0 < F) {
                    val = *(const float4*)(Agg + (size_t)n * F + k0 + kq * 4);
                    float s = sRD[m];
                    val.x *= s; val.y *= s; val.z *= s; val.w *= s;
                } else {
                    val = *(const float4*)(X + (size_t)n * F + (k0 - F) + kq * 4);
                }
            }
            pa[r] = val;
            int bk = v >> 5, boq = v & 31;
            pb[r] = ((const float4*)(Bw + (size_t)(k0 + bk) * 128))[boq];
        }
    };

    auto storeAB = [&]() {
#pragma unroll
        for (int r = 0; r < 2; r++) {
            int v = tid + 256 * r;
            int m = v >> 2, kq = v & 3;
            sA[(kq * 4 + 0) * 132 + m] = pa[r].x;
            sA[(kq * 4 + 1) * 132 + m] = pa[r].y;
            sA[(kq * 4 + 2) * 132 + m] = pa[r].z;
            sA[(kq * 4 + 3) * 132 + m] = pa[r].w;
            int bk = v >> 5, boq = v & 31;
            ((float4*)(sB + bk * 128))[boq] = pb[r];
        }
    };

    loadAB(0);
    for (int k0 = 0; k0 < K; k0 += KC) {
        storeAB();
        __syncthreads();
        if (k0 + KC < K) loadAB(k0 + KC);

#pragma unroll
        for (int kk = 0; kk < KC; kk++) {
            float a[8], b[8];
            *(float4*)(a)     = *(const float4*)(sA + kk * 132 + m0);
            *(float4*)(a + 4) = *(const float4*)(sA + kk * 132 + m0 + 4);
            *(float4*)(b)     = *(const float4*)(sB + kk * 128 + o0);
            *(float4*)(b + 4) = *(const float4*)(sB + kk * 128 + o0 + 4);
#pragma unroll
            for (int i = 0; i < 8; i++)
#pragma unroll
                for (int j = 0; j < 8; j++)
                    acc[i][j] += a[i] * b[j];
        }
        __syncthreads();
    }

    // epilogue
#pragma unroll
    for (int i = 0; i < 8; i++) {
        int n = nbase + m0 + i;
        if (n < N) {
            float4 v0, v1;
            if (RELU) {
                v0 = make_float4(fmaxf(acc[i][0], 0.f), fmaxf(acc[i][1], 0.f),
                                 fmaxf(acc[i][2], 0.f), fmaxf(acc[i][3], 0.f));
                v1 = make_float4(fmaxf(acc[i][4], 0.f), fmaxf(acc[i][5], 0.f),
                                 fmaxf(acc[i][6], 0.f), fmaxf(acc[i][7], 0.f));
            } else {
                v0 = make_float4(acc[i][0], acc[i][1], acc[i][2], acc[i][3]);
                v1 = make_float4(acc[i][4], acc[i][5], acc[i][6], acc[i][7]);
            }
            float4* dst = (float4*)(C + (size_t)n * 128 + o0);
            dst[0] = v0;
            dst[1] = v1;
        }
    }
}

// ---------------------------------------------------------------------------
extern "C" void kernel_launch(void* const* d_in, const int* in_sizes, int n_in,
                              void* d_out, int out_size) {
    const int*   edge = (const int*)d_in[0];
    const float* emb  = (const float*)d_in[1];
    const float* W1l  = (const float*)d_in[2];
    const float* b1l  = (const float*)d_in[3];
    const float* W1r  = (const float*)d_in[4];
    const float* W2l  = (const float*)d_in[5];
    const float* b2l  = (const float*)d_in[6];
    const float* W2r  = (const float*)d_in[7];
    float* out = (float*)d_out;

    int E = in_sizes[0] / 2;
    int N = in_sizes[1] / F1;
    const int* src = edge;
    const int* dst = edge + E;

    // zero scratch + pack weights
    {
        int n1 = N * (F1 / 4);
        int n2 = N * (F2 / 4);
        int nd = (N + 3) / 4;
        zero_kernel<<<(n2 + 255) / 256, 256>>>(n1, n2, nd);
        pack_kernel<<<(256 * 128 + 255) / 256, 256>>>(W1l, W1r, W2l, W2r);
    }

    // layer 1 aggregation (+ degree)
    {
        long long total = (long long)E * 16;
        scatter1_kernel<<<(int)((total + 255) / 256), 256>>>(src, dst, emb, E);
    }

    // layer 1: h = relu([mean1 | emb] @ B1 + b1l)
    {
        int blocks = (N + 127) / 128;
        gemm_kernel<128, true, true><<<blocks, 256>>>(emb, b1l, nullptr, N);
    }

    // layer 2 aggregation
    {
        long long total = (long long)E * 32;
        scatter2_kernel<<<(int)((total + 255) / 256), 256>>>(src, dst, E);
    }

    // layer 2: out = [mean2 | h] @ B2 + b2l
    {
        int blocks = (N + 127) / 128;
        gemm_kernel<256, false, false><<<blocks, 256>>>(nullptr, b2l, out, N);
    }
}